// round 16
// baseline (speedup 1.0000x reference)
#include <cuda_runtime.h>
#include <cuda_bf16.h>
#include <math.h>
#include <stdint.h>

// ===========================================================================
// CBTree B=4, L=9, d=256.
// h_par = tanh(G @ B^T + v),  G=[gl|gr] (M x 512),  B=[Wl|Wr] (256 x 512).
//   gl = c0 + (2/3)c1 + (1/3)c2 ;  gr = (1/3)c1 + (2/3)c2 + c3
// R16: wide l7 (proven fastest l7) + R8-depth mids (l6 z=2, l5 z=4) +
//      MLP-2 reduce + fused l1+l0 tail. 3-pass bf16 hi/lo HMMA throughout.
// ===========================================================================

#define MTILE 64

// ---- narrow kernel smem layout (24KB/stage) ----
#define N_A_HI 0
#define N_A_LO 4096
#define N_B_HI 8192
#define N_B_LO 16384
#define N_STAGE 24576
#define N_SMEM (2 * N_STAGE)   // 48 KB

// ---- wide kernel smem layout (40KB/stage) ----
#define W_A_HI 0
#define W_A_LO 4096
#define W_B_HI 8192
#define W_B_LO 24576
#define W_STAGE 40960
#define W_SMEM (2 * W_STAGE)   // 80 KB

#define SW(r, cb) ((uint32_t)((r) * 64 + (((cb) ^ (((r) >> 1) & 3)) << 4)))

__device__ float g_h0[16384 * 256];      // 16 MB h ping
__device__ float g_h1[16384 * 256];      // 16 MB h pong
__device__ float g_part[2097152];        // 8 MB K-split partials
__device__ uint4 g_Bhi[256 * 512 / 8];   // bf16 [256][512] hi of [Wl|Wr]
__device__ uint4 g_Blo[256 * 512 / 8];   // bf16 [256][512] lo

// ---------------------------------------------------------------------------
__device__ __forceinline__ uint32_t smem_u32(const void* p) {
    uint32_t a;
    asm("{ .reg .u64 t; cvta.to.shared.u64 t, %1; cvt.u32.u64 %0, t; }"
        : "=r"(a) : "l"(p));
    return a;
}
__device__ __forceinline__ void ldsm_x4(uint32_t* r, uint32_t addr) {
    asm volatile("ldmatrix.sync.aligned.m8n8.x4.shared.b16 {%0,%1,%2,%3}, [%4];"
                 : "=r"(r[0]), "=r"(r[1]), "=r"(r[2]), "=r"(r[3]) : "r"(addr));
}
__device__ __forceinline__ void mma16816(float* d, const uint32_t* a,
                                         const uint32_t* b) {
    asm volatile(
        "mma.sync.aligned.m16n8k16.row.col.f32.bf16.bf16.f32 "
        "{%0,%1,%2,%3}, {%4,%5,%6,%7}, {%8,%9}, {%0,%1,%2,%3};"
        : "+f"(d[0]), "+f"(d[1]), "+f"(d[2]), "+f"(d[3])
        : "r"(a[0]), "r"(a[1]), "r"(a[2]), "r"(a[3]), "r"(b[0]), "r"(b[1]));
}
__device__ __forceinline__ void cp_async16(uint32_t dst, const void* src) {
    asm volatile("cp.async.cg.shared.global [%0], [%1], 16;"
                 :: "r"(dst), "l"(src) : "memory");
}
#define CP_COMMIT() asm volatile("cp.async.commit_group;" ::: "memory")
#define CP_WAIT0()  asm volatile("cp.async.wait_group 0;" ::: "memory")

__device__ __forceinline__ void split2(float x, float y, uint32_t& hi, uint32_t& lo) {
    __nv_bfloat16 hx = __float2bfloat16(x);
    __nv_bfloat16 hy = __float2bfloat16(y);
    float rx = x - __bfloat162float(hx);
    float ry = y - __bfloat162float(hy);
    hi = (uint32_t)__bfloat16_as_ushort(hx) |
         ((uint32_t)__bfloat16_as_ushort(hy) << 16);
    lo = (uint32_t)__bfloat16_as_ushort(__float2bfloat16(rx)) |
         ((uint32_t)__bfloat16_as_ushort(__float2bfloat16(ry)) << 16);
}

// ---------------------------------------------------------------------------
__global__ void prep_b(const float* __restrict__ Wl, const float* __restrict__ Wr,
                       int base) {
    int idx = (base + blockIdx.x) * 256 + threadIdx.x;
    int n = idx >> 9, k = idx & 511;
    float w = (k < 256) ? Wl[n * 256 + k] : Wr[n * 256 + (k - 256)];
    __nv_bfloat16 h = __float2bfloat16(w);
    float r = w - __bfloat162float(h);
    ((unsigned short*)g_Bhi)[idx] = __bfloat16_as_ushort(h);
    ((unsigned short*)g_Blo)[idx] = __bfloat16_as_ushort(__float2bfloat16(r));
}

// ===========================================================================
// WIDE kernel (l7): 512 thr, CTA 64(M) x 256(N), in-loop A, fused epilogue.
// ===========================================================================
__global__ void __launch_bounds__(512) mma_l7(
    const float* __restrict__ childs,
    const float* __restrict__ vecs,
    float* __restrict__ out)
{
    extern __shared__ char smem[];
    const uint32_t sbase = smem_u32(smem);
    const int tid  = threadIdx.x;
    const int warp = tid >> 5;
    const int lane = tid & 31;
    const int wm   = warp & 1;
    const int wn   = warp >> 1;
    const int p0   = blockIdx.x * MTILE;

    const int fr  = tid >> 2, fcb = tid & 3;
    const uint32_t bswA = SW(fr, fcb);
    const uint32_t bswB = SW(128 + fr, fcb);
    const int giA = fr * 64 + fcb;
    const int giB = (128 + fr) * 64 + fcb;
    const bool aThread = (tid < 256);
    const uint32_t asw = bswA;
    const float* cbbase = childs + (size_t)(p0 + fr) * 1024 + fcb * 8;

    uint32_t aAddr[2][2], bAddr[2][2];
#pragma unroll
    for (int ks = 0; ks < 2; ks++) {
        const int acb = ks * 2 + (lane >> 4);
        const int arow = wm * 32 + (lane & 15);
#pragma unroll
        for (int mi = 0; mi < 2; mi++)
            aAddr[ks][mi] = sbase + W_A_HI + SW(arow + mi * 16, acb);
#pragma unroll
        for (int nq = 0; nq < 2; nq++) {
            const int brow = wn * 32 + nq * 16 + (lane & 15);
            bAddr[ks][nq] = sbase + W_B_HI + SW(brow, acb);
        }
    }

    float acc[2][4][4];
#pragma unroll
    for (int i = 0; i < 2; i++)
#pragma unroll
        for (int j = 0; j < 4; j++)
#pragma unroll
            for (int q = 0; q < 4; q++) acc[i][j][q] = 0.0f;

    float4 ra0, ra1, rb0, rb1, rd0, rd1;

    auto load_A = [&](int c) {
        if (!aThread) return;
        const bool left = (c < 8);
        const float* cb = cbbase + (left ? c * 32 : ((c - 8) * 32 + 256));
        ra0 = *(const float4*)(cb);
        ra1 = *(const float4*)(cb + 4);
        rb0 = *(const float4*)(cb + 256);
        rb1 = *(const float4*)(cb + 260);
        rd0 = *(const float4*)(cb + 512);
        rd1 = *(const float4*)(cb + 516);
    };
    auto store_A = [&](int c, uint32_t stOff) {
        if (!aThread) return;
        const bool left = (c < 8);
        const float w0 = left ? 1.0f : (1.0f / 3.0f);
        const float w1 = 2.0f / 3.0f;
        const float w2 = left ? (1.0f / 3.0f) : 1.0f;
        float g0 = w0 * ra0.x + w1 * rb0.x + w2 * rd0.x;
        float g1 = w0 * ra0.y + w1 * rb0.y + w2 * rd0.y;
        float g2 = w0 * ra0.z + w1 * rb0.z + w2 * rd0.z;
        float g3 = w0 * ra0.w + w1 * rb0.w + w2 * rd0.w;
        float g4 = w0 * ra1.x + w1 * rb1.x + w2 * rd1.x;
        float g5 = w0 * ra1.y + w1 * rb1.y + w2 * rd1.y;
        float g6 = w0 * ra1.z + w1 * rb1.z + w2 * rd1.z;
        float g7 = w0 * ra1.w + w1 * rb1.w + w2 * rd1.w;
        uint4 uh, ul;
        split2(g0, g1, uh.x, ul.x);
        split2(g2, g3, uh.y, ul.y);
        split2(g4, g5, uh.z, ul.z);
        split2(g6, g7, uh.w, ul.w);
        char* st = smem + stOff;
        *(uint4*)(st + W_A_HI + asw) = uh;
        *(uint4*)(st + W_A_LO + asw) = ul;
    };
    auto fill_B = [&](int c, uint32_t stOff) {
        const uint32_t st = sbase + stOff;
        const int cc = c * 4;
        cp_async16(st + W_B_HI + bswA, g_Bhi + giA + cc);
        cp_async16(st + W_B_LO + bswA, g_Blo + giA + cc);
        cp_async16(st + W_B_HI + bswB, g_Bhi + giB + cc);
        cp_async16(st + W_B_LO + bswB, g_Blo + giB + cc);
    };

    load_A(0);
    fill_B(0, 0);
    CP_COMMIT();
    store_A(0, 0);

    for (int i = 0; i < 16; i++) {
        const uint32_t sOff = (i & 1) ? W_STAGE : 0;
        const uint32_t sOffN = sOff ^ W_STAGE;
        CP_WAIT0();
        __syncthreads();

        const bool more = (i + 1 < 16);
        if (more) {
            load_A(i + 1);
            fill_B(i + 1, sOffN);
            CP_COMMIT();
        }

#pragma unroll
        for (int ks = 0; ks < 2; ks++) {
            uint32_t ah[2][4], al[2][4];
#pragma unroll
            for (int mi = 0; mi < 2; mi++) {
                const uint32_t ad = aAddr[ks][mi] + sOff;
                ldsm_x4(ah[mi], ad);
                ldsm_x4(al[mi], ad + (W_A_LO - W_A_HI));
            }
#pragma unroll
            for (int nq = 0; nq < 2; nq++) {
                const uint32_t bd = bAddr[ks][nq] + sOff;
                uint32_t qh[4], ql[4];
                ldsm_x4(qh, bd);
                ldsm_x4(ql, bd + (W_B_LO - W_B_HI));
                uint32_t bh0[2] = {qh[0], qh[2]}, bh1[2] = {qh[1], qh[3]};
                uint32_t bl0[2] = {ql[0], ql[2]}, bl1[2] = {ql[1], ql[3]};
#pragma unroll
                for (int mi = 0; mi < 2; mi++) {
                    mma16816(acc[mi][nq * 2],     ah[mi], bh0);
                    mma16816(acc[mi][nq * 2],     al[mi], bh0);
                    mma16816(acc[mi][nq * 2],     ah[mi], bl0);
                    mma16816(acc[mi][nq * 2 + 1], ah[mi], bh1);
                    mma16816(acc[mi][nq * 2 + 1], al[mi], bh1);
                    mma16816(acc[mi][nq * 2 + 1], ah[mi], bl1);
                }
            }
        }
        if (more) store_A(i + 1, sOffN);
    }

#pragma unroll
    for (int mi = 0; mi < 2; mi++) {
        const int r0 = p0 + wm * 32 + mi * 16 + (lane >> 2);
        const int r1 = r0 + 8;
#pragma unroll
        for (int nj = 0; nj < 4; nj++) {
            const int col = wn * 32 + nj * 8 + (lane & 3) * 2;
            float2 v0 = *(const float2*)(vecs + (size_t)r0 * 256 + col);
            float2 v1 = *(const float2*)(vecs + (size_t)r1 * 256 + col);
            float2 q0, q1;
            q0.x = tanhf(acc[mi][nj][0] + v0.x);
            q0.y = tanhf(acc[mi][nj][1] + v0.y);
            q1.x = tanhf(acc[mi][nj][2] + v1.x);
            q1.y = tanhf(acc[mi][nj][3] + v1.y);
            *(float2*)(out + (size_t)r0 * 256 + col) = q0;
            *(float2*)(out + (size_t)r1 * 256 + col) = q1;
        }
    }
}

// ===========================================================================
// NARROW kernel (l6/l5): 256 thr, CTA 64x128, 2 CTA/SM, K-split partials.
// ===========================================================================
struct ARegs { float4 a0, a1, b0, b1, d0, d1; };

__device__ __forceinline__ void n_load_A(int c, const float* __restrict__ childs,
                                         int p0, int tid, ARegs& ar) {
    const bool left = (c < 8);
    const int row = tid >> 2, cblk = tid & 3;
    const int j0 = (left ? c * 32 : (c - 8) * 32) + cblk * 8;
    const int o0 = left ? 0 : 256;
    const float* cb = childs + (size_t)(p0 + row) * 1024 + j0;
    ar.a0 = *(const float4*)(cb + o0);
    ar.a1 = *(const float4*)(cb + o0 + 4);
    ar.b0 = *(const float4*)(cb + o0 + 256);
    ar.b1 = *(const float4*)(cb + o0 + 260);
    ar.d0 = *(const float4*)(cb + o0 + 512);
    ar.d1 = *(const float4*)(cb + o0 + 516);
}

__device__ __forceinline__ void n_store_A(int c, const ARegs& ar, char* st, int tid) {
    const bool left = (c < 8);
    const float w0 = left ? 1.0f : (1.0f / 3.0f);
    const float w1 = 2.0f / 3.0f;
    const float w2 = left ? (1.0f / 3.0f) : 1.0f;
    float g0 = w0 * ar.a0.x + w1 * ar.b0.x + w2 * ar.d0.x;
    float g1 = w0 * ar.a0.y + w1 * ar.b0.y + w2 * ar.d0.y;
    float g2 = w0 * ar.a0.z + w1 * ar.b0.z + w2 * ar.d0.z;
    float g3 = w0 * ar.a0.w + w1 * ar.b0.w + w2 * ar.d0.w;
    float g4 = w0 * ar.a1.x + w1 * ar.b1.x + w2 * ar.d1.x;
    float g5 = w0 * ar.a1.y + w1 * ar.b1.y + w2 * ar.d1.y;
    float g6 = w0 * ar.a1.z + w1 * ar.b1.z + w2 * ar.d1.z;
    float g7 = w0 * ar.a1.w + w1 * ar.b1.w + w2 * ar.d1.w;
    uint4 uh, ul;
    split2(g0, g1, uh.x, ul.x);
    split2(g2, g3, uh.y, ul.y);
    split2(g4, g5, uh.z, ul.z);
    split2(g6, g7, uh.w, ul.w);
    const int row = tid >> 2, cblk = tid & 3;
    uint32_t sw = SW(row, cblk);
    *(uint4*)(st + N_A_HI + sw) = uh;
    *(uint4*)(st + N_A_LO + sw) = ul;
}

__device__ __forceinline__ void n_fill_B(uint32_t stage, int c, int n0, int tid) {
#pragma unroll
    for (int it = 0; it < 2; it++) {
        int idx  = it * 256 + tid;
        int row  = idx >> 2, cblk = idx & 3;
        int gi   = (n0 + row) * 64 + c * 4 + cblk;
        uint32_t sw = SW(row, cblk);
        cp_async16(stage + N_B_HI + sw, g_Bhi + gi);
        cp_async16(stage + N_B_LO + sw, g_Blo + gi);
    }
}

__global__ void __launch_bounds__(256, 2) mma_mid(
    const float* __restrict__ childs,
    float* __restrict__ part,
    int nc, size_t zstride)
{
    extern __shared__ char smem[];
    const uint32_t sbase = smem_u32(smem);
    const int tid  = threadIdx.x;
    const int warp = tid >> 5;
    const int lane = tid & 31;
    const int wm   = warp & 1;
    const int wn   = warp >> 1;
    const int p0   = blockIdx.x * MTILE;
    const int n0   = blockIdx.y * 128;
    const int c0   = blockIdx.z * nc;

    float acc[2][4][4];
#pragma unroll
    for (int i = 0; i < 2; i++)
#pragma unroll
        for (int j = 0; j < 4; j++)
#pragma unroll
            for (int q = 0; q < 4; q++) acc[i][j][q] = 0.0f;

    ARegs ar;
    n_load_A(c0, childs, p0, tid, ar);
    n_fill_B(sbase, c0, n0, tid);
    CP_COMMIT();
    n_store_A(c0, ar, smem, tid);

    for (int i = 0; i < nc; i++) {
        const int c = c0 + i;
        const int s = i & 1;
        CP_WAIT0();
        __syncthreads();

        const bool more = (i + 1 < nc);
        if (more) {
            n_load_A(c + 1, childs, p0, tid, ar);
            n_fill_B(sbase + (s ^ 1) * N_STAGE, c + 1, n0, tid);
            CP_COMMIT();
        }

        const uint32_t sA = sbase + s * N_STAGE;
#pragma unroll
        for (int ks = 0; ks < 2; ks++) {
            const int acb = ks * 2 + (lane >> 4);
            uint32_t ah[2][4], al[2][4];
            const int arow = wm * 32 + (lane & 15);
#pragma unroll
            for (int mi = 0; mi < 2; mi++) {
                uint32_t ad = sA + N_A_HI + SW(arow + mi * 16, acb);
                ldsm_x4(ah[mi], ad);
                ldsm_x4(al[mi], ad + (N_A_LO - N_A_HI));
            }
#pragma unroll
            for (int nq = 0; nq < 2; nq++) {
                const int brow = wn * 32 + nq * 16 + (lane & 15);
                uint32_t bd = sA + N_B_HI + SW(brow, acb);
                uint32_t qh[4], ql[4];
                ldsm_x4(qh, bd);
                ldsm_x4(ql, bd + (N_B_LO - N_B_HI));
                uint32_t bh0[2] = {qh[0], qh[2]}, bh1[2] = {qh[1], qh[3]};
                uint32_t bl0[2] = {ql[0], ql[2]}, bl1[2] = {ql[1], ql[3]};
#pragma unroll
                for (int mi = 0; mi < 2; mi++) {
                    mma16816(acc[mi][nq * 2],     ah[mi], bh0);
                    mma16816(acc[mi][nq * 2],     al[mi], bh0);
                    mma16816(acc[mi][nq * 2],     ah[mi], bl0);
                    mma16816(acc[mi][nq * 2 + 1], ah[mi], bh1);
                    mma16816(acc[mi][nq * 2 + 1], al[mi], bh1);
                    mma16816(acc[mi][nq * 2 + 1], ah[mi], bl1);
                }
            }
        }
        if (more) n_store_A(c + 1, ar, smem + (s ^ 1) * N_STAGE, tid);
        __syncthreads();
    }

    float* dst = part + (size_t)blockIdx.z * zstride;
#pragma unroll
    for (int mi = 0; mi < 2; mi++) {
        const int r0 = p0 + wm * 32 + mi * 16 + (lane >> 2);
        const int r1 = r0 + 8;
#pragma unroll
        for (int nj = 0; nj < 4; nj++) {
            const int col = n0 + wn * 32 + nj * 8 + (lane & 3) * 2;
            *(float2*)(dst + (size_t)r0 * 256 + col) =
                make_float2(acc[mi][nj][0], acc[mi][nj][1]);
            *(float2*)(dst + (size_t)r1 * 256 + col) =
                make_float2(acc[mi][nj][2], acc[mi][nj][3]);
        }
    }
}

// ---------------------------------------------------------------------------
// reduce: 2 independent float4 streams per thread (MLP 2x).
// grid = half4 / 256, where half4 = total_float4s / 2.
// ---------------------------------------------------------------------------
__global__ void __launch_bounds__(256) reduce_tanh2(
    const float* __restrict__ part, const float* __restrict__ vecs,
    float* __restrict__ out, int nsplit, size_t zstride, size_t half4)
{
    size_t i1 = (size_t)blockIdx.x * 256 + threadIdx.x;
    size_t i2 = i1 + half4;
    float4 s1 = ((const float4*)part)[i1];
    float4 s2 = ((const float4*)part)[i2];
    for (int z = 1; z < nsplit; z++) {
        const float* pz = part + (size_t)z * zstride;
        float4 t1 = ((const float4*)pz)[i1];
        float4 t2 = ((const float4*)pz)[i2];
        s1.x += t1.x; s1.y += t1.y; s1.z += t1.z; s1.w += t1.w;
        s2.x += t2.x; s2.y += t2.y; s2.z += t2.z; s2.w += t2.w;
    }
    float4 v1 = ((const float4*)vecs)[i1];
    float4 v2 = ((const float4*)vecs)[i2];
    float4 r1, r2;
    r1.x = tanhf(s1.x + v1.x); r1.y = tanhf(s1.y + v1.y);
    r1.z = tanhf(s1.z + v1.z); r1.w = tanhf(s1.w + v1.w);
    r2.x = tanhf(s2.x + v2.x); r2.y = tanhf(s2.y + v2.y);
    r2.z = tanhf(s2.z + v2.z); r2.w = tanhf(s2.w + v2.w);
    ((float4*)out)[i1] = r1;
    ((float4*)out)[i2] = r2;
}

// ---------------------------------------------------------------------------
__global__ void __launch_bounds__(256) level_small(
    const float* __restrict__ childs,
    const float* __restrict__ Wl,
    const float* __restrict__ Wr,
    const float* __restrict__ vecs,
    float* __restrict__ out)
{
    __shared__ float G[512];
    __shared__ float partl[8][33];
    const int tid = threadIdx.x;
    const int p   = blockIdx.x >> 3;
    const int cg  = blockIdx.x & 7;
    const float c23 = 2.0f / 3.0f, c13 = 1.0f / 3.0f;

    {
        const float* cb = childs + (size_t)p * 1024;
        int j = tid;
        G[j] = cb[j] + c23 * cb[256 + j] + c13 * cb[512 + j];
        G[256 + j] = c13 * cb[256 + j] + c23 * cb[512 + j] + cb[768 + j];
    }
    __syncthreads();

    const int cc = tid & 31;
    const int kg = tid >> 5;
    const int n  = cg * 32 + cc;
    const float* src = (kg < 4) ? (Wl + (size_t)n * 256 + kg * 64)
                                : (Wr + (size_t)n * 256 + (kg - 4) * 64);
    const float* g = G + kg * 64;

    float a0 = 0.f, a1 = 0.f, a2 = 0.f, a3 = 0.f;
#pragma unroll
    for (int i = 0; i < 64; i += 4) {
        float4 w = *(const float4*)(src + i);
        float4 gg = *(const float4*)(g + i);
        a0 = fmaf(gg.x, w.x, a0);
        a1 = fmaf(gg.y, w.y, a1);
        a2 = fmaf(gg.z, w.z, a2);
        a3 = fmaf(gg.w, w.w, a3);
    }
    partl[kg][cc] = (a0 + a1) + (a2 + a3);
    __syncthreads();

    if (tid < 32) {
        float s = 0.f;
#pragma unroll
        for (int k = 0; k < 8; k++) s += partl[k][tid];
        const int col = cg * 32 + tid;
        out[(size_t)p * 256 + col] = tanhf(s + vecs[(size_t)p * 256 + col]);
    }
}

// ---------------------------------------------------------------------------
// Fused l1 + l0: single CTA, 256 threads. h2 = 16 rows x 256.
// ---------------------------------------------------------------------------
__global__ void __launch_bounds__(256) tail_l1l0(
    const float* __restrict__ h2,
    const float* __restrict__ Wl,
    const float* __restrict__ Wr,
    const float* __restrict__ v1,
    const float* __restrict__ v0,
    float* __restrict__ out)
{
    __shared__ float G1[4 * 512];
    __shared__ float h1s[4 * 256];
    __shared__ float G0[512];
    const int tid = threadIdx.x;
    const float c23 = 2.0f / 3.0f, c13 = 1.0f / 3.0f;

    // build G1 for 4 parents (2048 entries)
    for (int e = tid; e < 2048; e += 256) {
        int p = e >> 9, j = e & 511;
        const float* cb = h2 + (size_t)p * 1024;
        float g;
        if (j < 256) g = cb[j] + c23 * cb[256 + j] + c13 * cb[512 + j];
        else {
            int q = j - 256;
            g = c13 * cb[256 + q] + c23 * cb[512 + q] + cb[768 + q];
        }
        G1[p * 512 + j] = g;
    }
    __syncthreads();

    // l1: thread tid = output col; 4 parents share W row tid
    {
        float a0 = 0.f, a1 = 0.f, a2 = 0.f, a3 = 0.f;
        const float* wlr = Wl + (size_t)tid * 256;
        const float* wrr = Wr + (size_t)tid * 256;
        for (int k = 0; k < 256; k++) {
            float wl = wlr[k], wr = wrr[k];
            a0 += G1[k] * wl + G1[256 + k] * wr;
            a1 += G1[512 + k] * wl + G1[768 + k] * wr;
            a2 += G1[1024 + k] * wl + G1[1280 + k] * wr;
            a3 += G1[1536 + k] * wl + G1[1792 + k] * wr;
        }
        h1s[tid]       = tanhf(a0 + v1[tid]);
        h1s[256 + tid] = tanhf(a1 + v1[256 + tid]);
        h1s[512 + tid] = tanhf(a2 + v1[512 + tid]);
        h1s[768 + tid] = tanhf(a3 + v1[768 + tid]);
    }
    __syncthreads();

    // G0
    G0[tid]       = h1s[tid] + c23 * h1s[256 + tid] + c13 * h1s[512 + tid];
    G0[256 + tid] = c13 * h1s[256 + tid] + c23 * h1s[512 + tid] + h1s[768 + tid];
    __syncthreads();

    // l0
    {
        float a = 0.f;
        const float* wlr = Wl + (size_t)tid * 256;
        const float* wrr = Wr + (size_t)tid * 256;
        for (int k = 0; k < 256; k++)
            a += G0[k] * wlr[k] + G0[256 + k] * wrr[k];
        out[tid] = tanhf(a + v0[tid]);
    }
}

// ---------------------------------------------------------------------------
extern "C" void kernel_launch(void* const* d_in, const int* in_sizes, int n_in,
                              void* d_out, int out_size) {
    const float* vectors = (const float*)d_in[0];
    const float* Wl = (const float*)d_in[1];
    const float* Wr = (const float*)d_in[2];

    static float *h0, *h1, *part;
    static bool inited = false;
    if (!inited) {
        cudaGetSymbolAddress((void**)&h0, g_h0);
        cudaGetSymbolAddress((void**)&h1, g_h1);
        cudaGetSymbolAddress((void**)&part, g_part);
        cudaFuncSetAttribute(mma_l7,
                             cudaFuncAttributeMaxDynamicSharedMemorySize, W_SMEM);
        cudaFuncSetAttribute(mma_mid,
                             cudaFuncAttributeMaxDynamicSharedMemorySize, N_SMEM);
        inited = true;
    }

    const float* leaves = vectors + (size_t)21845 * 256;
    const float* v7 = vectors + (size_t)5461 * 256;
    const float* v6 = vectors + (size_t)1365 * 256;
    const float* v5 = vectors + (size_t)341 * 256;
    const float* v4 = vectors + (size_t)85 * 256;
    const float* v3 = vectors + (size_t)21 * 256;
    const float* v2 = vectors + (size_t)5 * 256;
    const float* v1 = vectors + (size_t)1 * 256;
    const float* v0 = vectors;

    // slots 0-2: prep; slot 3 = mma_l7 (ncu capture)
    prep_b<<<171, 256>>>(Wl, Wr, 0);
    prep_b<<<171, 256>>>(Wl, Wr, 171);
    prep_b<<<170, 256>>>(Wl, Wr, 342);

    // l7: wide fused -> h7 (g_h0)
    mma_l7<<<256, 512, W_SMEM>>>(leaves, v7, h0);

    // l6: narrow z=2 (nc=8) -> 8MB partials -> h6 (g_h1)
    {
        size_t zs = (size_t)4096 * 256;         // floats per z-slice
        mma_mid<<<dim3(64, 2, 2), 256, N_SMEM>>>(h0, part, 8, zs);
        size_t half4 = zs / 8;                  // total f4 = zs/4; half = zs/8
        reduce_tanh2<<<(unsigned)(half4 / 256), 256>>>(part, v6, h1, 2, zs, half4);
    }
    // l5: narrow z=4 (nc=4) -> 4MB partials -> h5 (g_h0)
    {
        size_t zs = (size_t)1024 * 256;
        mma_mid<<<dim3(16, 2, 4), 256, N_SMEM>>>(h1, part, 4, zs);
        size_t half4 = zs / 8;
        reduce_tanh2<<<(unsigned)(half4 / 256), 256>>>(part, v5, h0, 4, zs, half4);
    }
    // l4..l2: fp32 SIMT chain
    level_small<<<256 * 8, 256>>>(h0, Wl, Wr, v4, h1);
    level_small<<<64 * 8, 256>>>(h1, Wl, Wr, v3, h0);
    level_small<<<16 * 8, 256>>>(h0, Wl, Wr, v2, h1);
    // l1 + l0 fused
    tail_l1l0<<<1, 256>>>(h1, Wl, Wr, v1, v0, (float*)d_out);
}